// round 14
// baseline (speedup 1.0000x reference)
#include <cuda_runtime.h>
#include <cuda_bf16.h>
#include <math.h>
#include <stdint.h>

#define NN 50000
#define NE 600000
#define CC 128
#define NLAYERS 15
#define NSTEPS 30
#define GTILE 782                 // ceil(NN/64) m-tiles
#define NTHR 256

#define STRD 136
#define ARRA 17408                // 64*STRD*2  (A array)
#define ARRB 34816                // 128*STRD*2 (B array)
#define SMTOT (2 * ARRA + 2 * ARRB)   // 104448 -> 2 CTAs/SM

// combo kernel block partition
#define CB_CONV 25000             // NN*CC/256
#define CB_WPREP 3840             // NSTEPS*128*256/256
#define CB_MASK 1
#define CB_HIST 2344              // ceil(NE/256)
#define CB_TOTAL (CB_CONV + CB_WPREP + CB_MASK + CB_HIST)

// ---------------- static scratch ----------------
__device__ float g_B0[NN * CC];          // layer-input x (residual source)
__device__ float g_HE[NN * CC];          // elu(x)
__device__ float g_P [NN * CC];          // Laplacian propagate
__device__ float g_partial[GTILE * CC];
__device__ float g_cvec[CC];
__device__ float g_masksum;
__device__ int   g_cnt[NN];              // invariant: zero at kernel_launch entry
__device__ int   g_rowptr[NN + 1];
__device__ int   g_cursor[NN];           // invariant: zero at kernel_launch entry
__device__ int2  g_edge[NE];
// weight bf16 hi/lo images: [step 30][n 128][k 256]
__device__ __nv_bfloat16 g_Wh[NSTEPS * 128 * 256];
__device__ __nv_bfloat16 g_Wl[NSTEPS * 128 * 256];

// ---------------- helpers ----------------
__device__ __forceinline__ uint32_t smem_u32(const void* p) {
    uint32_t a;
    asm("{ .reg .u64 t; cvta.to.shared.u64 t, %1; cvt.u32.u64 %0, t; }" : "=r"(a) : "l"(p));
    return a;
}
__device__ __forceinline__ float elu1(float x) {
    return x > 0.f ? x : (__expf(x) - 1.f);
}
__device__ __forceinline__ unsigned short bfbits(float x) {
    return __bfloat16_as_ushort(__float2bfloat16_rn(x));
}
__device__ __forceinline__ void ldsm_x4(uint32_t* r, uint32_t addr) {
    asm volatile("ldmatrix.sync.aligned.m8n8.x4.shared.b16 {%0,%1,%2,%3}, [%4];"
                 : "=r"(r[0]), "=r"(r[1]), "=r"(r[2]), "=r"(r[3]) : "r"(addr));
}
__device__ __forceinline__ void mma16816(float* d, const uint32_t* a, const uint32_t* b) {
    asm volatile("mma.sync.aligned.m16n8k16.row.col.f32.bf16.bf16.f32 "
                 "{%0,%1,%2,%3}, {%4,%5,%6,%7}, {%8,%9}, {%0,%1,%2,%3};"
                 : "+f"(d[0]), "+f"(d[1]), "+f"(d[2]), "+f"(d[3])
                 : "r"(a[0]), "r"(a[1]), "r"(a[2]), "r"(a[3]), "r"(b[0]), "r"(b[1]));
}
__device__ __forceinline__ void cp16(uint32_t dst, const void* src) {
    asm volatile("cp.async.cg.shared.global [%0], [%1], 16;" :: "r"(dst), "l"(src));
}
__device__ __forceinline__ void cp_commit() {
    asm volatile("cp.async.commit_group;" ::: "memory");
}
template <int N>
__device__ __forceinline__ void cp_wait_group() {
    asm volatile("cp.async.wait_group %0;" :: "n"(N) : "memory");
}

// one 128-wide K chunk of MMAs for a 16x64 warp tile (A arrays stride ARRA, B stride ARRB)
__device__ __forceinline__ void do_chunk(uint32_t aBase, uint32_t bBase, float acc[8][4]) {
#pragma unroll
    for (int ks = 0; ks < 8; ks++) {
        uint32_t ah[4], al[4], bh[4][4], bl[4][4];
        {
            uint32_t off = (uint32_t)(ks * 32);
            ldsm_x4(ah, aBase + off);
            ldsm_x4(al, aBase + ARRA + off);
        }
#pragma unroll
        for (int nfp = 0; nfp < 4; nfp++) {
            uint32_t off = (uint32_t)((nfp * 16 * STRD + ks * 16) * 2);
            ldsm_x4(bh[nfp], bBase + off);
            ldsm_x4(bl[nfp], bBase + ARRB + off);
        }
#pragma unroll
        for (int nfp = 0; nfp < 4; nfp++)
#pragma unroll
            for (int h = 0; h < 2; h++) {
                float* d = acc[nfp * 2 + h];
                mma16816(d, ah, &bh[nfp][h * 2]);
                mma16816(d, ah, &bl[nfp][h * 2]);
                mma16816(d, al, &bh[nfp][h * 2]);
            }
    }
}

// stage fp32 A chunk (64 rows x 128 cols) -> bf16 hi/lo smem; 256 thr: 4/row, 32 cols each
__device__ __forceinline__ void stage_A(const float* Ag, char* AH, int m0, int frow, int fcol,
                                        bool rowok) {
    const float* ap = Ag + (size_t)(m0 + frow) * CC + fcol;
    char* dh = AH + (frow * STRD + fcol) * 2;
    char* dl = dh + ARRA;
#pragma unroll
    for (int q = 0; q < 8; q++) {
        float4 v = rowok ? *(const float4*)(ap + q * 4) : make_float4(0.f, 0.f, 0.f, 0.f);
        unsigned short hx = bfbits(v.x), hy = bfbits(v.y), hz = bfbits(v.z), hw = bfbits(v.w);
        float lx = v.x - __bfloat162float(__ushort_as_bfloat16(hx));
        float ly = v.y - __bfloat162float(__ushort_as_bfloat16(hy));
        float lz = v.z - __bfloat162float(__ushort_as_bfloat16(hz));
        float lw = v.w - __bfloat162float(__ushort_as_bfloat16(hw));
        *(uint2*)(dh + q * 8) =
            make_uint2((uint32_t)hx | ((uint32_t)hy << 16), (uint32_t)hz | ((uint32_t)hw << 16));
        *(uint2*)(dl + q * 8) =
            make_uint2((uint32_t)bfbits(lx) | ((uint32_t)bfbits(ly) << 16),
                       (uint32_t)bfbits(lz) | ((uint32_t)bfbits(lw) << 16));
    }
}

// cp.async one prepped B chunk (128 n x 128 k); 256 thr: 2/row, 64 cols (128B) each array
__device__ __forceinline__ void stage_B_async(uint32_t sb, const __nv_bfloat16* Wh,
                                              const __nv_bfloat16* Wl, int kcol,
                                              int brow, int bcol) {
    uint32_t dh = sb + 2 * ARRA + (uint32_t)((brow * STRD + bcol) * 2);
    uint32_t dl = dh + ARRB;
    const char* gh = (const char*)(Wh + (size_t)brow * 256 + kcol + bcol);
    const char* gl = (const char*)(Wl + (size_t)brow * 256 + kcol + bcol);
#pragma unroll
    for (int q = 0; q < 8; q++) {
        cp16(dh + q * 16, gh + q * 16);
        cp16(dl + q * 16, gl + q * 16);
    }
}

// epilogue (4x2 warp grid, warp tile 16x64): bias (+res), x write, elu -> HE, partials
template <bool ADD_RES, bool RED>
__device__ __forceinline__ void epilogue(float acc[8][4], char* smem,
                                         const float* bias, const float* res,
                                         const float* mask,
                                         float* outx, float* outhe,
                                         int m0, int wm, int wn, int gid, int tid4,
                                         int tid, int lane, int mt) {
    float redv[16];
    float mval[2];
#pragma unroll
    for (int k = 0; k < 16; k++) redv[k] = 0.f;
    if (RED) {
#pragma unroll
        for (int hh = 0; hh < 2; hh++) {
            int row = m0 + wm * 16 + hh * 8 + gid;
            mval[hh] = (row < NN) ? mask[row] : 0.f;
        }
    }
#pragma unroll
    for (int hh = 0; hh < 2; hh++) {
        int row = m0 + wm * 16 + hh * 8 + gid;
        bool ok = row < NN;
#pragma unroll
        for (int nf = 0; nf < 8; nf++) {
            int col = wn * 64 + nf * 8 + tid4 * 2;
            float vx = acc[nf][hh * 2 + 0] + bias[col];
            float vy = acc[nf][hh * 2 + 1] + bias[col + 1];
            if (ADD_RES && ok) {
                float2 rr = *(const float2*)&res[(size_t)row * CC + col];
                vx += rr.x; vy += rr.y;
            }
            float hx = elu1(vx), hy = elu1(vy);
            if (ok) {
                if (ADD_RES)
                    *(float2*)&outx[(size_t)row * CC + col] = make_float2(vx, vy);
                *(float2*)&outhe[(size_t)row * CC + col] = make_float2(hx, hy);
            }
            if (RED) {
                redv[nf * 2 + 0] += hx * mval[hh];
                redv[nf * 2 + 1] += hy * mval[hh];
            }
        }
    }
    if (RED) {
#pragma unroll
        for (int o = 16; o >= 4; o >>= 1)
#pragma unroll
            for (int k = 0; k < 16; k++)
                redv[k] += __shfl_down_sync(0xffffffffu, redv[k], o);
        __syncthreads();
        float* sred = (float*)smem;      // [4 wm][128]
        if (lane < 4) {
#pragma unroll
            for (int nf = 0; nf < 8; nf++) {
                sred[wm * 128 + wn * 64 + nf * 8 + tid4 * 2 + 0] = redv[nf * 2 + 0];
                sred[wm * 128 + wn * 64 + nf * 8 + tid4 * 2 + 1] = redv[nf * 2 + 1];
            }
        }
        __syncthreads();
        if (tid < 128)
            g_partial[mt * CC + tid] =
                sred[tid] + sred[128 + tid] + sred[256 + tid] + sred[384 + tid];
    }
}

// ---------------- combo setup: conv1+elu | wprep | masksum | hist ----------------
__global__ void combo_kernel(const float* __restrict__ in, const float* __restrict__ W1,
                             const float* __restrict__ b1, const float* __restrict__ BW,
                             const float* __restrict__ mask, const int* __restrict__ Lrow,
                             float* __restrict__ X, float* __restrict__ HE) {
    int bid = blockIdx.x;
    if (bid < CB_CONV) {
        int t = bid * 256 + threadIdx.x;
        int n = t >> 7, c = t & 127;
        float x = in[n * 3 + 0] * W1[c] + in[n * 3 + 1] * W1[CC + c]
                + in[n * 3 + 2] * W1[2 * CC + c] + b1[c];
        X[t] = x;
        HE[t] = elu1(x);
    } else if (bid < CB_CONV + CB_WPREP) {
        int t = (bid - CB_CONV) * 256 + threadIdx.x;
        int step = t >> 15;
        int r = t & 32767;
        int n = r >> 8;
        int k = r & 255;
        float x = BW[(size_t)step * 256 * 128 + (size_t)k * 128 + n];
        __nv_bfloat16 h = __float2bfloat16_rn(x);
        g_Wh[t] = h;
        g_Wl[t] = __float2bfloat16_rn(x - __bfloat162float(h));
    } else if (bid < CB_CONV + CB_WPREP + CB_MASK) {
        __shared__ float s[256];
        float a = 0.f;
        for (int i = threadIdx.x; i < NN; i += 256) a += mask[i];
        s[threadIdx.x] = a;
        __syncthreads();
        for (int o = 128; o > 0; o >>= 1) {
            if (threadIdx.x < o) s[threadIdx.x] += s[threadIdx.x + o];
            __syncthreads();
        }
        if (threadIdx.x == 0) g_masksum = s[0];
    } else {
        int e = (bid - CB_CONV - CB_WPREP - CB_MASK) * 256 + threadIdx.x;
        if (e < NE) atomicAdd(&g_cnt[Lrow[e]], 1);
    }
}

// ---------------- single-block exclusive scan of cnt -> rowptr ----------------
__global__ void scan_one_kernel() {
    __shared__ float dummy;   (void)dummy;
    __shared__ int s[1024];
    int running = 0;
    for (int base = 0; base < NN; base += 1024) {
        int idx = base + threadIdx.x;
        int v = (idx < NN) ? g_cnt[idx] : 0;
        s[threadIdx.x] = v;
        __syncthreads();
        for (int off = 1; off < 1024; off <<= 1) {
            int t = (threadIdx.x >= off) ? s[threadIdx.x - off] : 0;
            __syncthreads();
            s[threadIdx.x] += t;
            __syncthreads();
        }
        if (idx < NN) g_rowptr[idx] = running + s[threadIdx.x] - v;   // exclusive
        int tot = s[1023];
        __syncthreads();
        running += tot;
    }
    if (threadIdx.x == 0) g_rowptr[NN] = running;
}

__global__ void fill_kernel(const int* __restrict__ row, const int* __restrict__ col,
                            const float* __restrict__ val) {
    int e = blockIdx.x * blockDim.x + threadIdx.x;
    if (e >= NE) return;
    int r = row[e];
    int pos = g_rowptr[r] + atomicAdd(&g_cursor[r], 1);
    g_edge[pos] = make_int2(col[e], __float_as_int(val[e]));
}
__global__ void tail_zero_kernel() {
    int i = blockIdx.x * blockDim.x + threadIdx.x;
    if (i < NN) { g_cnt[i] = 0; g_cursor[i] = 0; }
}

// ---------------- cvec = b + mean(elu(x)) @ W_bot ----------------
__global__ void cvec_kernel(const float* __restrict__ Wbot, const float* __restrict__ b) {
    __shared__ float sp[512];
    __shared__ float m[CC];
    int c = threadIdx.x & 127, part = threadIdx.x >> 7;
    float s = 0.f;
    for (int bi = part; bi < GTILE; bi += 4) s += g_partial[bi * CC + c];
    sp[threadIdx.x] = s;
    __syncthreads();
    if (threadIdx.x < 128)
        m[c] = (sp[c] + sp[128 + c] + sp[256 + c] + sp[384 + c]) / g_masksum;
    __syncthreads();
    float acc = 0.f;
    for (int k = part * 32; k < part * 32 + 32; k++) acc += m[k] * Wbot[k * CC + c];
    sp[threadIdx.x] = acc;
    __syncthreads();
    if (threadIdx.x < 128)
        g_cvec[c] = b[c] + sp[c] + sp[128 + c] + sp[256 + c] + sp[384 + c];
}

// ---------------- Laplacian segment-sum via CSR (int2 edges, unroll 4) --------------
__global__ void lap_kernel(const float* __restrict__ HE, float* __restrict__ P) {
    int warp = (blockIdx.x * blockDim.x + threadIdx.x) >> 5;
    int lane = threadIdx.x & 31;
    if (warp >= NN) return;
    int s = g_rowptr[warp], e1 = g_rowptr[warp + 1];
    const int lane4 = lane * 4;
    float4 acc = make_float4(0.f, 0.f, 0.f, 0.f);
    int e = s;
    for (; e + 4 <= e1; e += 4) {
        int2 ev0 = g_edge[e], ev1 = g_edge[e + 1], ev2 = g_edge[e + 2], ev3 = g_edge[e + 3];
        float4 h0 = *(const float4*)&HE[(size_t)ev0.x * CC + lane4];
        float4 h1 = *(const float4*)&HE[(size_t)ev1.x * CC + lane4];
        float4 h2 = *(const float4*)&HE[(size_t)ev2.x * CC + lane4];
        float4 h3 = *(const float4*)&HE[(size_t)ev3.x * CC + lane4];
        float v0 = __int_as_float(ev0.y), v1 = __int_as_float(ev1.y);
        float v2 = __int_as_float(ev2.y), v3 = __int_as_float(ev3.y);
        acc.x += v0 * h0.x + v1 * h1.x + v2 * h2.x + v3 * h3.x;
        acc.y += v0 * h0.y + v1 * h1.y + v2 * h2.y + v3 * h3.y;
        acc.z += v0 * h0.z + v1 * h1.z + v2 * h2.z + v3 * h3.z;
        acc.w += v0 * h0.w + v1 * h1.w + v2 * h2.w + v3 * h3.w;
    }
    for (; e < e1; e++) {
        int2 ev = g_edge[e];
        float v = __int_as_float(ev.y);
        float4 h = *(const float4*)&HE[(size_t)ev.x * CC + lane4];
        acc.x += v * h.x; acc.y += v * h.y; acc.z += v * h.z; acc.w += v * h.w;
    }
    *(float4*)&P[(size_t)warp * CC + lane4] = acc;
}

// ---------------- even-layer GEMM (K=256, A2 = P); M=64 tile, 2 CTAs/SM ------------
template <bool ADD_RES, bool RED>
__global__ __launch_bounds__(NTHR, 2)
void gemm_lap(const float* __restrict__ A1, const float* __restrict__ A2,
              const __nv_bfloat16* __restrict__ Wh, const __nv_bfloat16* __restrict__ Wl,
              const float* __restrict__ bias, const float* __restrict__ res,
              const float* __restrict__ mask,
              float* __restrict__ outx, float* __restrict__ outhe) {
    extern __shared__ char smem[];
    const uint32_t sb = smem_u32(smem);
    const int tid = threadIdx.x;
    const int wid = tid >> 5, lane = tid & 31;
    const int wm = wid & 3, wn = wid >> 2;     // 4 x 2 warp grid, tile 16x64
    const int m0 = blockIdx.x * 64;
    const int gid = lane >> 2, tid4 = lane & 3;
    const int frow = tid >> 2;                 // A: 4 thr/row over 64 rows
    const int fcol = (tid & 3) * 32;
    const int brow = tid >> 1;                 // B: 2 thr/row over 128 rows
    const int bcol = (tid & 1) * 64;
    const bool rowok = (m0 + frow) < NN;

    stage_B_async(sb, Wh, Wl, 0, brow, bcol);
    cp_commit();
    stage_A(A1, smem, m0, frow, fcol, rowok);
    cp_wait_group<0>();
    __syncthreads();

    float acc[8][4] = {};
    const uint32_t aOff = (uint32_t)(((wm * 16 + (lane & 15)) * STRD + (lane >> 4) * 8) * 2);
    const uint32_t bOff = 2 * ARRA +
        (uint32_t)(((wn * 64 + (lane & 7) + ((lane >> 4) * 8)) * STRD + ((lane >> 3) & 1) * 8) * 2);
    do_chunk(sb + aOff, sb + bOff, acc);
    __syncthreads();

    stage_B_async(sb, Wh, Wl, 128, brow, bcol);
    cp_commit();
    stage_A(A2, smem, m0, frow, fcol, rowok);
    cp_wait_group<0>();
    __syncthreads();
    do_chunk(sb + aOff, sb + bOff, acc);

    epilogue<ADD_RES, RED>(acc, smem, bias, res, mask, outx, outhe,
                           m0, wm, wn, gid, tid4, tid, lane, blockIdx.x);
}

// ---------------- odd-layer GEMM (K=128); M=64 tile ----------------
template <bool ADD_RES, bool RED>
__global__ __launch_bounds__(NTHR, 2)
void gemm_avg(const float* __restrict__ A1,
              const __nv_bfloat16* __restrict__ Wh, const __nv_bfloat16* __restrict__ Wl,
              const float* __restrict__ bias, const float* __restrict__ res,
              const float* __restrict__ mask,
              float* __restrict__ outx, float* __restrict__ outhe) {
    extern __shared__ char smem[];
    const uint32_t sb = smem_u32(smem);
    const int tid = threadIdx.x;
    const int wid = tid >> 5, lane = tid & 31;
    const int wm = wid & 3, wn = wid >> 2;
    const int m0 = blockIdx.x * 64;
    const int gid = lane >> 2, tid4 = lane & 3;
    const int frow = tid >> 2;
    const int fcol = (tid & 3) * 32;
    const int brow = tid >> 1;
    const int bcol = (tid & 1) * 64;
    const bool rowok = (m0 + frow) < NN;

    stage_B_async(sb, Wh, Wl, 0, brow, bcol);
    cp_commit();
    stage_A(A1, smem, m0, frow, fcol, rowok);
    cp_wait_group<0>();
    __syncthreads();

    float acc[8][4] = {};
    const uint32_t aOff = (uint32_t)(((wm * 16 + (lane & 15)) * STRD + (lane >> 4) * 8) * 2);
    const uint32_t bOff = 2 * ARRA +
        (uint32_t)(((wn * 64 + (lane & 7) + ((lane >> 4) * 8)) * STRD + ((lane >> 3) & 1) * 8) * 2);
    do_chunk(sb + aOff, sb + bOff, acc);

    epilogue<ADD_RES, RED>(acc, smem, bias, res, mask, outx, outhe,
                           m0, wm, wn, gid, tid4, tid, lane, blockIdx.x);
}

// ---------------- final ----------------
__global__ void final_kernel(const float* __restrict__ HE, const float* __restrict__ W2,
                             const float* __restrict__ b2, const float* __restrict__ in,
                             float* __restrict__ out) {
    int warp = (blockIdx.x * blockDim.x + threadIdx.x) >> 5;
    int lane = threadIdx.x & 31;
    if (warp >= NN) return;
    float4 x = *(const float4*)&HE[(size_t)warp * CC + lane * 4];
    float4 w = *(const float4*)&W2[lane * 4];
    float s = x.x * w.x + x.y * w.y + x.z * w.z + x.w * w.w;
#pragma unroll
    for (int o = 16; o > 0; o >>= 1) s += __shfl_down_sync(0xffffffffu, s, o);
    if (lane == 0) out[warp] = s + b2[0] + in[warp * 3];
}

// ---------------- host launch ----------------
extern "C" void kernel_launch(void* const* d_in, const int* in_sizes, int n_in,
                              void* d_out, int out_size) {
    const int*   L_row  = (const int*)d_in[0];
    const int*   L_col  = (const int*)d_in[1];
    const float* L_val  = (const float*)d_in[2];
    const float* mask   = (const float*)d_in[3];
    const float* inputs = (const float*)d_in[4];
    const float* W1     = (const float*)d_in[5];
    const float* b1     = (const float*)d_in[6];
    const float* BW     = (const float*)d_in[7];
    const float* Bb     = (const float*)d_in[8];
    const float* W2     = (const float*)d_in[9];
    const float* b2     = (const float*)d_in[10];
    float* out = (float*)d_out;

    float *B0, *HE, *P, *cvec;
    __nv_bfloat16 *Wh, *Wl;
    cudaGetSymbolAddress((void**)&B0, g_B0);
    cudaGetSymbolAddress((void**)&HE, g_HE);
    cudaGetSymbolAddress((void**)&P,  g_P);
    cudaGetSymbolAddress((void**)&cvec, g_cvec);
    cudaGetSymbolAddress((void**)&Wh, g_Wh);
    cudaGetSymbolAddress((void**)&Wl, g_Wl);

    static bool attr_done = false;
    if (!attr_done) {
        cudaFuncSetAttribute(gemm_lap<false, false>, cudaFuncAttributeMaxDynamicSharedMemorySize, SMTOT);
        cudaFuncSetAttribute(gemm_lap<true,  true>,  cudaFuncAttributeMaxDynamicSharedMemorySize, SMTOT);
        cudaFuncSetAttribute(gemm_lap<true,  false>, cudaFuncAttributeMaxDynamicSharedMemorySize, SMTOT);
        cudaFuncSetAttribute(gemm_avg<false, true>,  cudaFuncAttributeMaxDynamicSharedMemorySize, SMTOT);
        cudaFuncSetAttribute(gemm_avg<true,  false>, cudaFuncAttributeMaxDynamicSharedMemorySize, SMTOT);
        attr_done = true;
    }

    // ---- setup: combo(1) scan_one(2) fill(3); lap(4)=captured; gemms... ----
    combo_kernel<<<CB_TOTAL, 256>>>(inputs, W1, b1, BW, mask, L_row, B0, HE);
    scan_one_kernel<<<1, 1024>>>();
    fill_kernel<<<(NE + 255) / 256, 256>>>(L_row, L_col, L_val);

    const int LAP_GRID = (NN * 32 + 255) / 256;

    for (int i = 0; i < NLAYERS; i++) {
        for (int j = 0; j < 2; j++) {
            int step = i * 2 + j;
            const __nv_bfloat16* Whs = Wh + (size_t)step * 128 * 256;
            const __nv_bfloat16* Wls = Wl + (size_t)step * 128 * 256;
            const float* b = Bb + (size_t)step * CC;
            bool last = (step == NSTEPS - 1);

            if ((i & 1) == 0) {
                lap_kernel<<<LAP_GRID, 256>>>(HE, P);
                if (j == 0)
                    gemm_lap<false, false><<<GTILE, NTHR, SMTOT>>>(
                        HE, P, Whs, Wls, b, nullptr, mask, nullptr, HE);
                else if (!last)
                    gemm_lap<true, true><<<GTILE, NTHR, SMTOT>>>(
                        HE, P, Whs, Wls, b, B0, mask, B0, HE);
                else
                    gemm_lap<true, false><<<GTILE, NTHR, SMTOT>>>(
                        HE, P, Whs, Wls, b, B0, mask, B0, HE);
            } else {
                cvec_kernel<<<1, 512>>>(BW + (size_t)step * 256 * CC + 128 * CC, b);
                if (j == 0)
                    gemm_avg<false, true><<<GTILE, NTHR, SMTOT>>>(
                        HE, Whs, Wls, cvec, nullptr, mask, nullptr, HE);
                else
                    gemm_avg<true, false><<<GTILE, NTHR, SMTOT>>>(
                        HE, Whs, Wls, cvec, B0, mask, B0, HE);
            }
        }
    }

    final_kernel<<<(NN * 32 + 1023) / 1024, 1024>>>(HE, W2, b2, inputs, out);
    tail_zero_kernel<<<(NN + 255) / 256, 256>>>();

    (void)in_sizes; (void)n_in; (void)out_size;
}

// round 15
// speedup vs baseline: 1.1984x; 1.1984x over previous
#include <cuda_runtime.h>
#include <cuda_bf16.h>
#include <math.h>
#include <stdint.h>

#define NN 50000
#define NE 600000
#define CC 128
#define NLAYERS 15
#define NSTEPS 30
#define GGRID 391                 // ceil(NN/128)
#define NTHR 512

#define SCAN_CHUNK 512
#define SCAN_NCHUNK 98

#define STRD 136
#define ARR  34816                // 128*STRD*2 bytes
#define SMTOT_L (6 * ARR)         // even gemm: AH AL B0H B0L B1H B1L
#define SMTOT_O (4 * ARR)         // odd gemm: AH AL BH BL

// ---------------- static scratch ----------------
__device__ float g_B0[NN * CC];          // layer-input x (residual source)
__device__ float g_HE[NN * CC];          // elu(x)
__device__ float g_P [NN * CC];          // Laplacian propagate
__device__ float g_partial[GGRID * CC];
__device__ float g_cvec[CC];
__device__ float g_masksum;
__device__ int   g_cnt[NN];
__device__ int   g_rowptr[NN + 1];
__device__ int   g_cursor[NN];
__device__ int2  g_edge[NE];             // (col, val bits)
__device__ int   g_chunksum[SCAN_NCHUNK];
// weight bf16 hi/lo images: [step 30][n 128][k 256]
__device__ __nv_bfloat16 g_Wh[NSTEPS * 128 * 256];
__device__ __nv_bfloat16 g_Wl[NSTEPS * 128 * 256];

// ---------------- helpers ----------------
__device__ __forceinline__ uint32_t smem_u32(const void* p) {
    uint32_t a;
    asm("{ .reg .u64 t; cvta.to.shared.u64 t, %1; cvt.u32.u64 %0, t; }" : "=r"(a) : "l"(p));
    return a;
}
__device__ __forceinline__ float elu1(float x) {
    return x > 0.f ? x : (__expf(x) - 1.f);
}
__device__ __forceinline__ unsigned short bfbits(float x) {
    return __bfloat16_as_ushort(__float2bfloat16_rn(x));
}
__device__ __forceinline__ void ldsm_x4(uint32_t* r, uint32_t addr) {
    asm volatile("ldmatrix.sync.aligned.m8n8.x4.shared.b16 {%0,%1,%2,%3}, [%4];"
                 : "=r"(r[0]), "=r"(r[1]), "=r"(r[2]), "=r"(r[3]) : "r"(addr));
}
__device__ __forceinline__ void mma16816(float* d, const uint32_t* a, const uint32_t* b) {
    asm volatile("mma.sync.aligned.m16n8k16.row.col.f32.bf16.bf16.f32 "
                 "{%0,%1,%2,%3}, {%4,%5,%6,%7}, {%8,%9}, {%0,%1,%2,%3};"
                 : "+f"(d[0]), "+f"(d[1]), "+f"(d[2]), "+f"(d[3])
                 : "r"(a[0]), "r"(a[1]), "r"(a[2]), "r"(a[3]), "r"(b[0]), "r"(b[1]));
}
__device__ __forceinline__ void cp16(uint32_t dst, const void* src) {
    asm volatile("cp.async.cg.shared.global [%0], [%1], 16;" :: "r"(dst), "l"(src));
}
__device__ __forceinline__ void cp_commit() {
    asm volatile("cp.async.commit_group;" ::: "memory");
}
template <int N>
__device__ __forceinline__ void cp_wait_group() {
    asm volatile("cp.async.wait_group %0;" :: "n"(N) : "memory");
}

// one 128-wide K chunk of MMAs for a 16x64 warp tile (hi/lo split: 3 products)
__device__ __forceinline__ void do_chunk(uint32_t aBase, uint32_t bBase, float acc[8][4]) {
#pragma unroll
    for (int ks = 0; ks < 8; ks++) {
        uint32_t ah[4], al[4], bh[4][4], bl[4][4];
        {
            uint32_t off = (uint32_t)(ks * 32);
            ldsm_x4(ah, aBase + off);
            ldsm_x4(al, aBase + ARR + off);
        }
#pragma unroll
        for (int nfp = 0; nfp < 4; nfp++) {
            uint32_t off = (uint32_t)((nfp * 16 * STRD + ks * 16) * 2);
            ldsm_x4(bh[nfp], bBase + off);
            ldsm_x4(bl[nfp], bBase + ARR + off);
        }
#pragma unroll
        for (int nfp = 0; nfp < 4; nfp++)
#pragma unroll
            for (int h = 0; h < 2; h++) {
                float* d = acc[nfp * 2 + h];
                mma16816(d, ah, &bh[nfp][h * 2]);
                mma16816(d, ah, &bl[nfp][h * 2]);
                mma16816(d, al, &bh[nfp][h * 2]);
            }
    }
}

// stage fp32 A chunk (128 rows x 128 cols) -> bf16 hi/lo smem; 512 thr: 4/row, 32 cols each
__device__ __forceinline__ void stage_A(const float* Ag, char* AH, int m0, int frow, int fcol,
                                        bool rowok) {
    const float* ap = Ag + (size_t)(m0 + frow) * CC + fcol;
    char* dh = AH + (frow * STRD + fcol) * 2;
    char* dl = dh + ARR;
#pragma unroll
    for (int q = 0; q < 8; q++) {
        float4 v = rowok ? *(const float4*)(ap + q * 4) : make_float4(0.f, 0.f, 0.f, 0.f);
        unsigned short hx = bfbits(v.x), hy = bfbits(v.y), hz = bfbits(v.z), hw = bfbits(v.w);
        float lx = v.x - __bfloat162float(__ushort_as_bfloat16(hx));
        float ly = v.y - __bfloat162float(__ushort_as_bfloat16(hy));
        float lz = v.z - __bfloat162float(__ushort_as_bfloat16(hz));
        float lw = v.w - __bfloat162float(__ushort_as_bfloat16(hw));
        *(uint2*)(dh + q * 8) =
            make_uint2((uint32_t)hx | ((uint32_t)hy << 16), (uint32_t)hz | ((uint32_t)hw << 16));
        *(uint2*)(dl + q * 8) =
            make_uint2((uint32_t)bfbits(lx) | ((uint32_t)bfbits(ly) << 16),
                       (uint32_t)bfbits(lz) | ((uint32_t)bfbits(lw) << 16));
    }
}

// cp.async one prepped B pair (hi at dstOff, lo at dstOff+ARR); 512 thr: 32 cols each
__device__ __forceinline__ void stage_B_async(uint32_t sb, uint32_t dstOff,
                                              const __nv_bfloat16* Wh, const __nv_bfloat16* Wl,
                                              int kcol, int frow, int fcol) {
    uint32_t dh = sb + dstOff + (uint32_t)((frow * STRD + fcol) * 2);
    uint32_t dl = dh + ARR;
    const char* gh = (const char*)(Wh + (size_t)frow * 256 + kcol + fcol);
    const char* gl = (const char*)(Wl + (size_t)frow * 256 + kcol + fcol);
#pragma unroll
    for (int q = 0; q < 4; q++) {
        cp16(dh + q * 16, gh + q * 16);
        cp16(dl + q * 16, gl + q * 16);
    }
}

// epilogue for 16 warps (warp tile 16x64): bias (+res), optional x write, elu -> HE, partials
template <bool ADD_RES, bool RED, bool WRITE_X>
__device__ __forceinline__ void epilogue(float acc[8][4], char* smem,
                                         const float* bias, const float* res,
                                         const float* mask,
                                         float* outx, float* outhe,
                                         int m0, int wm, int wn, int gid, int tid4,
                                         int tid, int lane, int bid) {
    float redv[16];
    float mval[2];
#pragma unroll
    for (int k = 0; k < 16; k++) redv[k] = 0.f;
    if (RED) {
#pragma unroll
        for (int hh = 0; hh < 2; hh++) {
            int row = m0 + wm * 16 + hh * 8 + gid;
            mval[hh] = (row < NN) ? mask[row] : 0.f;
        }
    }
#pragma unroll
    for (int hh = 0; hh < 2; hh++) {
        int row = m0 + wm * 16 + hh * 8 + gid;
        bool ok = row < NN;
#pragma unroll
        for (int nf = 0; nf < 8; nf++) {
            int col = wn * 64 + nf * 8 + tid4 * 2;
            float vx = acc[nf][hh * 2 + 0] + bias[col];
            float vy = acc[nf][hh * 2 + 1] + bias[col + 1];
            if (ADD_RES && ok) {
                float2 rr = *(const float2*)&res[(size_t)row * CC + col];
                vx += rr.x; vy += rr.y;
            }
            float hx = elu1(vx), hy = elu1(vy);
            if (ok) {
                if (WRITE_X)
                    *(float2*)&outx[(size_t)row * CC + col] = make_float2(vx, vy);
                *(float2*)&outhe[(size_t)row * CC + col] = make_float2(hx, hy);
            }
            if (RED) {
                redv[nf * 2 + 0] += hx * mval[hh];
                redv[nf * 2 + 1] += hy * mval[hh];
            }
        }
    }
    if (RED) {
#pragma unroll
        for (int o = 16; o >= 4; o >>= 1)
#pragma unroll
            for (int k = 0; k < 16; k++)
                redv[k] += __shfl_down_sync(0xffffffffu, redv[k], o);
        __syncthreads();
        float* sred = (float*)smem;      // [8 wm][128]
        if (lane < 4) {
#pragma unroll
            for (int nf = 0; nf < 8; nf++) {
                sred[wm * 128 + wn * 64 + nf * 8 + tid4 * 2 + 0] = redv[nf * 2 + 0];
                sred[wm * 128 + wn * 64 + nf * 8 + tid4 * 2 + 1] = redv[nf * 2 + 1];
            }
        }
        __syncthreads();
        if (tid < 128) {
            float s = 0.f;
#pragma unroll
            for (int w = 0; w < 8; w++) s += sred[w * 128 + tid];
            g_partial[bid * CC + tid] = s;
        }
    }
}

// ---------------- CSR build ----------------
__global__ void zero2_kernel() {
    int i = blockIdx.x * blockDim.x + threadIdx.x;
    if (i < NN) { g_cnt[i] = 0; g_cursor[i] = 0; }
}
__global__ void hist_kernel(const int* __restrict__ row) {
    int e = blockIdx.x * blockDim.x + threadIdx.x;
    if (e < NE) atomicAdd(&g_cnt[row[e]], 1);
}
__global__ void scan1_kernel() {
    __shared__ int s[SCAN_CHUNK];
    int idx = blockIdx.x * SCAN_CHUNK + threadIdx.x;
    int v = (idx < NN) ? g_cnt[idx] : 0;
    s[threadIdx.x] = v;
    __syncthreads();
    for (int off = 1; off < SCAN_CHUNK; off <<= 1) {
        int t = (threadIdx.x >= off) ? s[threadIdx.x - off] : 0;
        __syncthreads();
        s[threadIdx.x] += t;
        __syncthreads();
    }
    if (idx < NN) g_rowptr[idx] = s[threadIdx.x];
    if (threadIdx.x == SCAN_CHUNK - 1) g_chunksum[blockIdx.x] = s[SCAN_CHUNK - 1];
}
__global__ void scan23_kernel() {
    __shared__ int off;
    if (threadIdx.x == 0) {
        int run = 0;
        for (int q = 0; q < blockIdx.x; q++) run += g_chunksum[q];
        off = run;
        if (blockIdx.x == SCAN_NCHUNK - 1) g_rowptr[NN] = run + g_chunksum[blockIdx.x];
    }
    __syncthreads();
    int idx = blockIdx.x * SCAN_CHUNK + threadIdx.x;
    if (idx < NN)
        g_rowptr[idx] = off + g_rowptr[idx] - g_cnt[idx];
}
__global__ void fill_kernel(const int* __restrict__ row, const int* __restrict__ col,
                            const float* __restrict__ val) {
    int e = blockIdx.x * blockDim.x + threadIdx.x;
    if (e >= NE) return;
    int r = row[e];
    int pos = g_rowptr[r] + atomicAdd(&g_cursor[r], 1);
    g_edge[pos] = make_int2(col[e], __float_as_int(val[e]));
}
__global__ void masksum_kernel(const float* __restrict__ mask) {
    __shared__ float s[1024];
    float a = 0.f;
    for (int i = threadIdx.x; i < NN; i += 1024) a += mask[i];
    s[threadIdx.x] = a;
    __syncthreads();
    for (int o = 512; o > 0; o >>= 1) {
        if (threadIdx.x < o) s[threadIdx.x] += s[threadIdx.x + o];
        __syncthreads();
    }
    if (threadIdx.x == 0) g_masksum = s[0];
}

// ---------------- weight prep ----------------
__global__ void wprep_kernel(const float* __restrict__ BW) {
    int t = blockIdx.x * blockDim.x + threadIdx.x;
    if (t >= NSTEPS * 128 * 256) return;
    int step = t >> 15;
    int r = t & 32767;
    int n = r >> 8;
    int k = r & 255;
    float x = BW[(size_t)step * 256 * 128 + (size_t)k * 128 + n];
    __nv_bfloat16 h = __float2bfloat16_rn(x);
    float lo = x - __bfloat162float(h);
    g_Wh[t] = h;
    g_Wl[t] = __float2bfloat16_rn(lo);
}

// ---------------- conv1 (+fused elu) ----------------
__global__ void conv1_kernel(const float* __restrict__ in, const float* __restrict__ W,
                             const float* __restrict__ b, float* __restrict__ X,
                             float* __restrict__ HE) {
    int t = blockIdx.x * blockDim.x + threadIdx.x;
    if (t >= NN * CC) return;
    int n = t >> 7, c = t & 127;
    float x = in[n * 3 + 0] * W[c] + in[n * 3 + 1] * W[CC + c] + in[n * 3 + 2] * W[2 * CC + c] + b[c];
    X[t] = x;
    HE[t] = elu1(x);
}

// ---------------- cvec = b + mean(elu(x)) @ W_bot ----------------
__global__ void cvec_kernel(const float* __restrict__ Wbot, const float* __restrict__ b) {
    __shared__ float sp[512];
    __shared__ float m[CC];
    int c = threadIdx.x & 127, part = threadIdx.x >> 7;
    float s = 0.f;
    for (int bi = part; bi < GGRID; bi += 4) s += g_partial[bi * CC + c];
    sp[threadIdx.x] = s;
    __syncthreads();
    if (threadIdx.x < 128)
        m[c] = (sp[c] + sp[128 + c] + sp[256 + c] + sp[384 + c]) / g_masksum;
    __syncthreads();
    float acc = 0.f;
    for (int k = part * 32; k < part * 32 + 32; k++) acc += m[k] * Wbot[k * CC + c];
    sp[threadIdx.x] = acc;
    __syncthreads();
    if (threadIdx.x < 128)
        g_cvec[c] = b[c] + sp[c] + sp[128 + c] + sp[256 + c] + sp[384 + c];
}

// ---------------- Laplacian segment-sum via CSR (int2 edges, unroll 8) --------------
__global__ void lap_kernel(const float* __restrict__ HE, float* __restrict__ P) {
    int warp = (blockIdx.x * blockDim.x + threadIdx.x) >> 5;
    int lane = threadIdx.x & 31;
    if (warp >= NN) return;
    int s = g_rowptr[warp], e1 = g_rowptr[warp + 1];
    const int lane4 = lane * 4;
    float4 acc = make_float4(0.f, 0.f, 0.f, 0.f);
    int e = s;
    for (; e + 8 <= e1; e += 8) {
        int2 ev[8];
#pragma unroll
        for (int q = 0; q < 8; q++) ev[q] = g_edge[e + q];
        float4 h[8];
#pragma unroll
        for (int q = 0; q < 8; q++) h[q] = *(const float4*)&HE[(size_t)ev[q].x * CC + lane4];
#pragma unroll
        for (int q = 0; q < 8; q++) {
            float v = __int_as_float(ev[q].y);
            acc.x += v * h[q].x; acc.y += v * h[q].y;
            acc.z += v * h[q].z; acc.w += v * h[q].w;
        }
    }
    for (; e + 4 <= e1; e += 4) {
        int2 ev0 = g_edge[e], ev1 = g_edge[e + 1], ev2 = g_edge[e + 2], ev3 = g_edge[e + 3];
        float4 h0 = *(const float4*)&HE[(size_t)ev0.x * CC + lane4];
        float4 h1 = *(const float4*)&HE[(size_t)ev1.x * CC + lane4];
        float4 h2 = *(const float4*)&HE[(size_t)ev2.x * CC + lane4];
        float4 h3 = *(const float4*)&HE[(size_t)ev3.x * CC + lane4];
        float v0 = __int_as_float(ev0.y), v1 = __int_as_float(ev1.y);
        float v2 = __int_as_float(ev2.y), v3 = __int_as_float(ev3.y);
        acc.x += v0 * h0.x + v1 * h1.x + v2 * h2.x + v3 * h3.x;
        acc.y += v0 * h0.y + v1 * h1.y + v2 * h2.y + v3 * h3.y;
        acc.z += v0 * h0.z + v1 * h1.z + v2 * h2.z + v3 * h3.z;
        acc.w += v0 * h0.w + v1 * h1.w + v2 * h2.w + v3 * h3.w;
    }
    for (; e < e1; e++) {
        int2 ev = g_edge[e];
        float v = __int_as_float(ev.y);
        float4 h = *(const float4*)&HE[(size_t)ev.x * CC + lane4];
        acc.x += v * h.x; acc.y += v * h.y; acc.z += v * h.z; acc.w += v * h.w;
    }
    *(float4*)&P[(size_t)warp * CC + lane4] = acc;
}

// ---------------- even-layer GEMM (K=256, A2 = P) ----------------
template <bool ADD_RES, bool RED, bool WRITE_X>
__global__ __launch_bounds__(NTHR, 1)
void gemm_lap(const float* __restrict__ A1, const float* __restrict__ A2,
              const __nv_bfloat16* __restrict__ Wh, const __nv_bfloat16* __restrict__ Wl,
              const float* __restrict__ bias, const float* __restrict__ res,
              const float* __restrict__ mask,
              float* __restrict__ outx, float* __restrict__ outhe) {
    extern __shared__ char smem[];
    const uint32_t sb = smem_u32(smem);
    const int tid = threadIdx.x;
    const int wid = tid >> 5, lane = tid & 31;
    const int wm = wid & 7, wn = wid >> 3;     // 8 x 2 warp grid, tile 16x64
    const int m0 = blockIdx.x * 128;
    const int gid = lane >> 2, tid4 = lane & 3;
    const int frow = tid >> 2;
    const int fcol = (tid & 3) * 32;
    const bool rowok = (m0 + frow) < NN;

    stage_B_async(sb, 2 * ARR, Wh, Wl, 0,   frow, fcol);
    cp_commit();
    stage_B_async(sb, 4 * ARR, Wh, Wl, 128, frow, fcol);
    cp_commit();

    stage_A(A1, smem, m0, frow, fcol, rowok);
    cp_wait_group<1>();
    __syncthreads();

    float acc[8][4] = {};
    const uint32_t aOff = (uint32_t)(((wm * 16 + (lane & 15)) * STRD + (lane >> 4) * 8) * 2);
    const uint32_t bOff = (uint32_t)(((wn * 64 + (lane & 7) + ((lane >> 4) * 8)) * STRD +
                                      ((lane >> 3) & 1) * 8) * 2);
    do_chunk(sb + aOff, sb + 2 * ARR + bOff, acc);
    __syncthreads();

    stage_A(A2, smem, m0, frow, fcol, rowok);
    cp_wait_group<0>();
    __syncthreads();
    do_chunk(sb + aOff, sb + 4 * ARR + bOff, acc);

    epilogue<ADD_RES, RED, WRITE_X>(acc, smem, bias, res, mask, outx, outhe,
                                    m0, wm, wn, gid, tid4, tid, lane, blockIdx.x);
}

// ---------------- odd-layer GEMM (K=128) ----------------
template <bool ADD_RES, bool RED, bool WRITE_X>
__global__ __launch_bounds__(NTHR, 1)
void gemm_avg(const float* __restrict__ A1,
              const __nv_bfloat16* __restrict__ Wh, const __nv_bfloat16* __restrict__ Wl,
              const float* __restrict__ bias, const float* __restrict__ res,
              const float* __restrict__ mask,
              float* __restrict__ outx, float* __restrict__ outhe) {
    extern __shared__ char smem[];
    const uint32_t sb = smem_u32(smem);
    const int tid = threadIdx.x;
    const int wid = tid >> 5, lane = tid & 31;
    const int wm = wid & 7, wn = wid >> 3;
    const int m0 = blockIdx.x * 128;
    const int gid = lane >> 2, tid4 = lane & 3;
    const int frow = tid >> 2;
    const int fcol = (tid & 3) * 32;
    const bool rowok = (m0 + frow) < NN;

    stage_B_async(sb, 2 * ARR, Wh, Wl, 0, frow, fcol);
    cp_commit();
    stage_A(A1, smem, m0, frow, fcol, rowok);
    cp_wait_group<0>();
    __syncthreads();

    float acc[8][4] = {};
    const uint32_t aOff = (uint32_t)(((wm * 16 + (lane & 15)) * STRD + (lane >> 4) * 8) * 2);
    const uint32_t bOff = (uint32_t)(((wn * 64 + (lane & 7) + ((lane >> 4) * 8)) * STRD +
                                      ((lane >> 3) & 1) * 8) * 2);
    do_chunk(sb + aOff, sb + 2 * ARR + bOff, acc);

    epilogue<ADD_RES, RED, WRITE_X>(acc, smem, bias, res, mask, outx, outhe,
                                    m0, wm, wn, gid, tid4, tid, lane, blockIdx.x);
}

// ---------------- final ----------------
__global__ void final_kernel(const float* __restrict__ HE, const float* __restrict__ W2,
                             const float* __restrict__ b2, const float* __restrict__ in,
                             float* __restrict__ out) {
    int warp = (blockIdx.x * blockDim.x + threadIdx.x) >> 5;
    int lane = threadIdx.x & 31;
    if (warp >= NN) return;
    float4 x = *(const float4*)&HE[(size_t)warp * CC + lane * 4];
    float4 w = *(const float4*)&W2[lane * 4];
    float s = x.x * w.x + x.y * w.y + x.z * w.z + x.w * w.w;
#pragma unroll
    for (int o = 16; o > 0; o >>= 1) s += __shfl_down_sync(0xffffffffu, s, o);
    if (lane == 0) out[warp] = s + b2[0] + in[warp * 3];
}

// ---------------- host launch ----------------
extern "C" void kernel_launch(void* const* d_in, const int* in_sizes, int n_in,
                              void* d_out, int out_size) {
    const int*   L_row  = (const int*)d_in[0];
    const int*   L_col  = (const int*)d_in[1];
    const float* L_val  = (const float*)d_in[2];
    const float* mask   = (const float*)d_in[3];
    const float* inputs = (const float*)d_in[4];
    const float* W1     = (const float*)d_in[5];
    const float* b1     = (const float*)d_in[6];
    const float* BW     = (const float*)d_in[7];
    const float* Bb     = (const float*)d_in[8];
    const float* W2     = (const float*)d_in[9];
    const float* b2     = (const float*)d_in[10];
    float* out = (float*)d_out;

    float *B0, *HE, *P, *cvec;
    __nv_bfloat16 *Wh, *Wl;
    cudaGetSymbolAddress((void**)&B0, g_B0);
    cudaGetSymbolAddress((void**)&HE, g_HE);
    cudaGetSymbolAddress((void**)&P,  g_P);
    cudaGetSymbolAddress((void**)&cvec, g_cvec);
    cudaGetSymbolAddress((void**)&Wh, g_Wh);
    cudaGetSymbolAddress((void**)&Wl, g_Wl);

    static bool attr_done = false;
    if (!attr_done) {
        cudaFuncSetAttribute(gemm_lap<false, false, false>, cudaFuncAttributeMaxDynamicSharedMemorySize, SMTOT_L);
        cudaFuncSetAttribute(gemm_lap<true,  true,  true>,  cudaFuncAttributeMaxDynamicSharedMemorySize, SMTOT_L);
        cudaFuncSetAttribute(gemm_lap<true,  false, false>, cudaFuncAttributeMaxDynamicSharedMemorySize, SMTOT_L);
        cudaFuncSetAttribute(gemm_avg<false, true,  false>, cudaFuncAttributeMaxDynamicSharedMemorySize, SMTOT_O);
        cudaFuncSetAttribute(gemm_avg<true,  false, true>,  cudaFuncAttributeMaxDynamicSharedMemorySize, SMTOT_O);
        attr_done = true;
    }

    // ---- setup (per replay), R7 layout ----
    zero2_kernel<<<(NN + 255) / 256, 256>>>();
    hist_kernel<<<(NE + 255) / 256, 256>>>(L_row);
    scan1_kernel<<<SCAN_NCHUNK, SCAN_CHUNK>>>();
    scan23_kernel<<<SCAN_NCHUNK, SCAN_CHUNK>>>();
    fill_kernel<<<(NE + 255) / 256, 256>>>(L_row, L_col, L_val);
    masksum_kernel<<<1, 1024>>>(mask);
    wprep_kernel<<<(NSTEPS * 128 * 256 + 255) / 256, 256>>>(BW);

    conv1_kernel<<<(NN * CC + 255) / 256, 256>>>(inputs, W1, b1, B0, HE);

    const int LAP_GRID = (NN * 32 + 255) / 256;

    for (int i = 0; i < NLAYERS; i++) {
        for (int j = 0; j < 2; j++) {
            int step = i * 2 + j;
            const __nv_bfloat16* Whs = Wh + (size_t)step * 128 * 256;
            const __nv_bfloat16* Wls = Wl + (size_t)step * 128 * 256;
            const float* b = Bb + (size_t)step * CC;
            bool last = (step == NSTEPS - 1);

            if ((i & 1) == 0) {
                lap_kernel<<<LAP_GRID, 256>>>(HE, P);
                if (j == 0)
                    gemm_lap<false, false, false><<<GGRID, NTHR, SMTOT_L>>>(
                        HE, P, Whs, Wls, b, nullptr, mask, nullptr, HE);
                else if (!last)
                    gemm_lap<true, true, true><<<GGRID, NTHR, SMTOT_L>>>(
                        HE, P, Whs, Wls, b, B0, mask, B0, HE);
                else
                    // last step: residual read from B0, but x is never read again -> skip write
                    gemm_lap<true, false, false><<<GGRID, NTHR, SMTOT_L>>>(
                        HE, P, Whs, Wls, b, B0, mask, nullptr, HE);
            } else {
                cvec_kernel<<<1, 512>>>(BW + (size_t)step * 256 * CC + 128 * CC, b);
                if (j == 0)
                    gemm_avg<false, true, false><<<GGRID, NTHR, SMTOT_O>>>(
                        HE, Whs, Wls, cvec, nullptr, mask, nullptr, HE);
                else
                    gemm_avg<true, false, true><<<GGRID, NTHR, SMTOT_O>>>(
                        HE, Whs, Wls, cvec, B0, mask, B0, HE);
            }
        }
    }

    final_kernel<<<(NN * 32 + 1023) / 1024, 1024>>>(HE, W2, b2, inputs, out);

    (void)in_sizes; (void)n_in; (void)out_size;
}

// round 16
// speedup vs baseline: 1.1990x; 1.0005x over previous
#include <cuda_runtime.h>
#include <cuda_bf16.h>
#include <math.h>
#include <stdint.h>

#define NN 50000
#define NE 600000
#define CC 128
#define NLAYERS 15
#define NSTEPS 30
#define GGRID 391                 // ceil(NN/128)
#define NTHR 512

#define SCAN_CHUNK 512
#define SCAN_NCHUNK 98

#define STRD 136
#define ARR  34816                // 128*STRD*2 bytes
#define SMTOT_L (6 * ARR)         // even gemm: AH AL B0H B0L B1H B1L
#define SMTOT_O (4 * ARR)         // odd gemm: AH AL BH BL

// ---------------- static scratch ----------------
__device__ float g_B0[NN * CC];          // layer-input x (residual source)
__device__ float g_HE[NN * CC];          // elu(x)
__device__ float g_P [NN * CC];          // Laplacian propagate
__device__ float g_partial[GGRID * CC];
__device__ float g_cvec[CC];
__device__ float g_masksum;
__device__ int   g_cnt[NN];
__device__ int   g_rowptr[NN + 1];
__device__ int   g_cursor[NN];
__device__ int2  g_edge[NE];             // (col, val bits)
__device__ int   g_chunksum[SCAN_NCHUNK];
// weight bf16 hi/lo images: [step 30][n 128][k 256]
__device__ __nv_bfloat16 g_Wh[NSTEPS * 128 * 256];
__device__ __nv_bfloat16 g_Wl[NSTEPS * 128 * 256];

// ---------------- helpers ----------------
__device__ __forceinline__ uint32_t smem_u32(const void* p) {
    uint32_t a;
    asm("{ .reg .u64 t; cvta.to.shared.u64 t, %1; cvt.u32.u64 %0, t; }" : "=r"(a) : "l"(p));
    return a;
}
__device__ __forceinline__ float elu1(float x) {
    return x > 0.f ? x : (__expf(x) - 1.f);
}
__device__ __forceinline__ unsigned short bfbits(float x) {
    return __bfloat16_as_ushort(__float2bfloat16_rn(x));
}
__device__ __forceinline__ void ldsm_x4(uint32_t* r, uint32_t addr) {
    asm volatile("ldmatrix.sync.aligned.m8n8.x4.shared.b16 {%0,%1,%2,%3}, [%4];"
                 : "=r"(r[0]), "=r"(r[1]), "=r"(r[2]), "=r"(r[3]) : "r"(addr));
}
__device__ __forceinline__ void mma16816(float* d, const uint32_t* a, const uint32_t* b) {
    asm volatile("mma.sync.aligned.m16n8k16.row.col.f32.bf16.bf16.f32 "
                 "{%0,%1,%2,%3}, {%4,%5,%6,%7}, {%8,%9}, {%0,%1,%2,%3};"
                 : "+f"(d[0]), "+f"(d[1]), "+f"(d[2]), "+f"(d[3])
                 : "r"(a[0]), "r"(a[1]), "r"(a[2]), "r"(a[3]), "r"(b[0]), "r"(b[1]));
}
__device__ __forceinline__ void cp16(uint32_t dst, const void* src) {
    asm volatile("cp.async.cg.shared.global [%0], [%1], 16;" :: "r"(dst), "l"(src));
}
__device__ __forceinline__ void cp_commit() {
    asm volatile("cp.async.commit_group;" ::: "memory");
}
template <int N>
__device__ __forceinline__ void cp_wait_group() {
    asm volatile("cp.async.wait_group %0;" :: "n"(N) : "memory");
}

// one 128-wide K chunk of MMAs for a 16x64 warp tile (hi/lo split: 3 products)
__device__ __forceinline__ void do_chunk(uint32_t aBase, uint32_t bBase, float acc[8][4]) {
#pragma unroll
    for (int ks = 0; ks < 8; ks++) {
        uint32_t ah[4], al[4], bh[4][4], bl[4][4];
        {
            uint32_t off = (uint32_t)(ks * 32);
            ldsm_x4(ah, aBase + off);
            ldsm_x4(al, aBase + ARR + off);
        }
#pragma unroll
        for (int nfp = 0; nfp < 4; nfp++) {
            uint32_t off = (uint32_t)((nfp * 16 * STRD + ks * 16) * 2);
            ldsm_x4(bh[nfp], bBase + off);
            ldsm_x4(bl[nfp], bBase + ARR + off);
        }
#pragma unroll
        for (int nfp = 0; nfp < 4; nfp++)
#pragma unroll
            for (int h = 0; h < 2; h++) {
                float* d = acc[nfp * 2 + h];
                mma16816(d, ah, &bh[nfp][h * 2]);
                mma16816(d, ah, &bl[nfp][h * 2]);
                mma16816(d, al, &bh[nfp][h * 2]);
            }
    }
}

// LDG one A chunk into registers: 4 thr/row, 32 cols each (8 x float4)
__device__ __forceinline__ void ldg_A(float4* aP, const float* Ag, int m0, int frow, int fcol,
                                      bool rowok) {
    const float* ap = Ag + (size_t)(m0 + frow) * CC + fcol;
#pragma unroll
    for (int q = 0; q < 8; q++)
        aP[q] = rowok ? *(const float4*)(ap + q * 4) : make_float4(0.f, 0.f, 0.f, 0.f);
}
// cvt + STS registers -> bf16 hi/lo smem
__device__ __forceinline__ void sts_A(const float4* aP, char* AH, int frow, int fcol) {
    char* dh = AH + (frow * STRD + fcol) * 2;
    char* dl = dh + ARR;
#pragma unroll
    for (int q = 0; q < 8; q++) {
        float4 v = aP[q];
        unsigned short hx = bfbits(v.x), hy = bfbits(v.y), hz = bfbits(v.z), hw = bfbits(v.w);
        float lx = v.x - __bfloat162float(__ushort_as_bfloat16(hx));
        float ly = v.y - __bfloat162float(__ushort_as_bfloat16(hy));
        float lz = v.z - __bfloat162float(__ushort_as_bfloat16(hz));
        float lw = v.w - __bfloat162float(__ushort_as_bfloat16(hw));
        *(uint2*)(dh + q * 8) =
            make_uint2((uint32_t)hx | ((uint32_t)hy << 16), (uint32_t)hz | ((uint32_t)hw << 16));
        *(uint2*)(dl + q * 8) =
            make_uint2((uint32_t)bfbits(lx) | ((uint32_t)bfbits(ly) << 16),
                       (uint32_t)bfbits(lz) | ((uint32_t)bfbits(lw) << 16));
    }
}
__device__ __forceinline__ void stage_A(const float* Ag, char* AH, int m0, int frow, int fcol,
                                        bool rowok) {
    float4 aP[8];
    ldg_A(aP, Ag, m0, frow, fcol, rowok);
    sts_A(aP, AH, frow, fcol);
}

// cp.async one prepped B pair (hi at dstOff, lo at dstOff+ARR); 512 thr: 32 cols each
__device__ __forceinline__ void stage_B_async(uint32_t sb, uint32_t dstOff,
                                              const __nv_bfloat16* Wh, const __nv_bfloat16* Wl,
                                              int kcol, int frow, int fcol) {
    uint32_t dh = sb + dstOff + (uint32_t)((frow * STRD + fcol) * 2);
    uint32_t dl = dh + ARR;
    const char* gh = (const char*)(Wh + (size_t)frow * 256 + kcol + fcol);
    const char* gl = (const char*)(Wl + (size_t)frow * 256 + kcol + fcol);
#pragma unroll
    for (int q = 0; q < 4; q++) {
        cp16(dh + q * 16, gh + q * 16);
        cp16(dl + q * 16, gl + q * 16);
    }
}

// prefetch epilogue residuals into registers (2 hh x 8 nf float2)
__device__ __forceinline__ void ldg_res(float2 rr[2][8], const float* res,
                                        int m0, int wm, int wn, int gid, int tid4) {
#pragma unroll
    for (int hh = 0; hh < 2; hh++) {
        int row = m0 + wm * 16 + hh * 8 + gid;
        bool ok = row < NN;
#pragma unroll
        for (int nf = 0; nf < 8; nf++) {
            int col = wn * 64 + nf * 8 + tid4 * 2;
            rr[hh][nf] = ok ? *(const float2*)&res[(size_t)row * CC + col]
                            : make_float2(0.f, 0.f);
        }
    }
}

// epilogue for 16 warps (warp tile 16x64): bias (+res regs), optional x write, elu, partials
template <bool ADD_RES, bool RED, bool WRITE_X>
__device__ __forceinline__ void epilogue(float acc[8][4], const float2 rr[2][8], char* smem,
                                         const float* bias, const float* mask,
                                         float* outx, float* outhe,
                                         int m0, int wm, int wn, int gid, int tid4,
                                         int tid, int lane, int bid) {
    float redv[16];
    float mval[2];
#pragma unroll
    for (int k = 0; k < 16; k++) redv[k] = 0.f;
    if (RED) {
#pragma unroll
        for (int hh = 0; hh < 2; hh++) {
            int row = m0 + wm * 16 + hh * 8 + gid;
            mval[hh] = (row < NN) ? mask[row] : 0.f;
        }
    }
#pragma unroll
    for (int hh = 0; hh < 2; hh++) {
        int row = m0 + wm * 16 + hh * 8 + gid;
        bool ok = row < NN;
#pragma unroll
        for (int nf = 0; nf < 8; nf++) {
            int col = wn * 64 + nf * 8 + tid4 * 2;
            float vx = acc[nf][hh * 2 + 0] + bias[col];
            float vy = acc[nf][hh * 2 + 1] + bias[col + 1];
            if (ADD_RES) {
                vx += rr[hh][nf].x; vy += rr[hh][nf].y;
            }
            float hx = elu1(vx), hy = elu1(vy);
            if (ok) {
                if (WRITE_X)
                    *(float2*)&outx[(size_t)row * CC + col] = make_float2(vx, vy);
                *(float2*)&outhe[(size_t)row * CC + col] = make_float2(hx, hy);
            }
            if (RED) {
                redv[nf * 2 + 0] += hx * mval[hh];
                redv[nf * 2 + 1] += hy * mval[hh];
            }
        }
    }
    if (RED) {
#pragma unroll
        for (int o = 16; o >= 4; o >>= 1)
#pragma unroll
            for (int k = 0; k < 16; k++)
                redv[k] += __shfl_down_sync(0xffffffffu, redv[k], o);
        __syncthreads();
        float* sred = (float*)smem;      // [8 wm][128]
        if (lane < 4) {
#pragma unroll
            for (int nf = 0; nf < 8; nf++) {
                sred[wm * 128 + wn * 64 + nf * 8 + tid4 * 2 + 0] = redv[nf * 2 + 0];
                sred[wm * 128 + wn * 64 + nf * 8 + tid4 * 2 + 1] = redv[nf * 2 + 1];
            }
        }
        __syncthreads();
        if (tid < 128) {
            float s = 0.f;
#pragma unroll
            for (int w = 0; w < 8; w++) s += sred[w * 128 + tid];
            g_partial[bid * CC + tid] = s;
        }
    }
}

// ---------------- CSR build ----------------
__global__ void zero2_kernel() {
    int i = blockIdx.x * blockDim.x + threadIdx.x;
    if (i < NN) { g_cnt[i] = 0; g_cursor[i] = 0; }
}
__global__ void hist_kernel(const int* __restrict__ row) {
    int e = blockIdx.x * blockDim.x + threadIdx.x;
    if (e < NE) atomicAdd(&g_cnt[row[e]], 1);
}
__global__ void scan1_kernel() {
    __shared__ int s[SCAN_CHUNK];
    int idx = blockIdx.x * SCAN_CHUNK + threadIdx.x;
    int v = (idx < NN) ? g_cnt[idx] : 0;
    s[threadIdx.x] = v;
    __syncthreads();
    for (int off = 1; off < SCAN_CHUNK; off <<= 1) {
        int t = (threadIdx.x >= off) ? s[threadIdx.x - off] : 0;
        __syncthreads();
        s[threadIdx.x] += t;
        __syncthreads();
    }
    if (idx < NN) g_rowptr[idx] = s[threadIdx.x];
    if (threadIdx.x == SCAN_CHUNK - 1) g_chunksum[blockIdx.x] = s[SCAN_CHUNK - 1];
}
__global__ void scan23_kernel() {
    __shared__ int off;
    if (threadIdx.x == 0) {
        int run = 0;
        for (int q = 0; q < blockIdx.x; q++) run += g_chunksum[q];
        off = run;
        if (blockIdx.x == SCAN_NCHUNK - 1) g_rowptr[NN] = run + g_chunksum[blockIdx.x];
    }
    __syncthreads();
    int idx = blockIdx.x * SCAN_CHUNK + threadIdx.x;
    if (idx < NN)
        g_rowptr[idx] = off + g_rowptr[idx] - g_cnt[idx];
}
__global__ void fill_kernel(const int* __restrict__ row, const int* __restrict__ col,
                            const float* __restrict__ val) {
    int e = blockIdx.x * blockDim.x + threadIdx.x;
    if (e >= NE) return;
    int r = row[e];
    int pos = g_rowptr[r] + atomicAdd(&g_cursor[r], 1);
    g_edge[pos] = make_int2(col[e], __float_as_int(val[e]));
}
__global__ void masksum_kernel(const float* __restrict__ mask) {
    __shared__ float s[1024];
    float a = 0.f;
    for (int i = threadIdx.x; i < NN; i += 1024) a += mask[i];
    s[threadIdx.x] = a;
    __syncthreads();
    for (int o = 512; o > 0; o >>= 1) {
        if (threadIdx.x < o) s[threadIdx.x] += s[threadIdx.x + o];
        __syncthreads();
    }
    if (threadIdx.x == 0) g_masksum = s[0];
}

// ---------------- weight prep ----------------
__global__ void wprep_kernel(const float* __restrict__ BW) {
    int t = blockIdx.x * blockDim.x + threadIdx.x;
    if (t >= NSTEPS * 128 * 256) return;
    int step = t >> 15;
    int r = t & 32767;
    int n = r >> 8;
    int k = r & 255;
    float x = BW[(size_t)step * 256 * 128 + (size_t)k * 128 + n];
    __nv_bfloat16 h = __float2bfloat16_rn(x);
    float lo = x - __bfloat162float(h);
    g_Wh[t] = h;
    g_Wl[t] = __float2bfloat16_rn(lo);
}

// ---------------- conv1 (+fused elu) ----------------
__global__ void conv1_kernel(const float* __restrict__ in, const float* __restrict__ W,
                             const float* __restrict__ b, float* __restrict__ X,
                             float* __restrict__ HE) {
    int t = blockIdx.x * blockDim.x + threadIdx.x;
    if (t >= NN * CC) return;
    int n = t >> 7, c = t & 127;
    float x = in[n * 3 + 0] * W[c] + in[n * 3 + 1] * W[CC + c] + in[n * 3 + 2] * W[2 * CC + c] + b[c];
    X[t] = x;
    HE[t] = elu1(x);
}

// ---------------- cvec = b + mean(elu(x)) @ W_bot ----------------
__global__ void cvec_kernel(const float* __restrict__ Wbot, const float* __restrict__ b) {
    __shared__ float sp[512];
    __shared__ float m[CC];
    int c = threadIdx.x & 127, part = threadIdx.x >> 7;
    float s = 0.f;
    for (int bi = part; bi < GGRID; bi += 4) s += g_partial[bi * CC + c];
    sp[threadIdx.x] = s;
    __syncthreads();
    if (threadIdx.x < 128)
        m[c] = (sp[c] + sp[128 + c] + sp[256 + c] + sp[384 + c]) / g_masksum;
    __syncthreads();
    float acc = 0.f;
    for (int k = part * 32; k < part * 32 + 32; k++) acc += m[k] * Wbot[k * CC + c];
    sp[threadIdx.x] = acc;
    __syncthreads();
    if (threadIdx.x < 128)
        g_cvec[c] = b[c] + sp[c] + sp[128 + c] + sp[256 + c] + sp[384 + c];
}

// ---------------- Laplacian segment-sum via CSR (int2 edges, unroll 8) --------------
__global__ void lap_kernel(const float* __restrict__ HE, float* __restrict__ P) {
    int warp = (blockIdx.x * blockDim.x + threadIdx.x) >> 5;
    int lane = threadIdx.x & 31;
    if (warp >= NN) return;
    int s = g_rowptr[warp], e1 = g_rowptr[warp + 1];
    const int lane4 = lane * 4;
    float4 acc = make_float4(0.f, 0.f, 0.f, 0.f);
    int e = s;
    for (; e + 8 <= e1; e += 8) {
        int2 ev[8];
#pragma unroll
        for (int q = 0; q < 8; q++) ev[q] = g_edge[e + q];
        float4 h[8];
#pragma unroll
        for (int q = 0; q < 8; q++) h[q] = *(const float4*)&HE[(size_t)ev[q].x * CC + lane4];
#pragma unroll
        for (int q = 0; q < 8; q++) {
            float v = __int_as_float(ev[q].y);
            acc.x += v * h[q].x; acc.y += v * h[q].y;
            acc.z += v * h[q].z; acc.w += v * h[q].w;
        }
    }
    for (; e + 4 <= e1; e += 4) {
        int2 ev0 = g_edge[e], ev1 = g_edge[e + 1], ev2 = g_edge[e + 2], ev3 = g_edge[e + 3];
        float4 h0 = *(const float4*)&HE[(size_t)ev0.x * CC + lane4];
        float4 h1 = *(const float4*)&HE[(size_t)ev1.x * CC + lane4];
        float4 h2 = *(const float4*)&HE[(size_t)ev2.x * CC + lane4];
        float4 h3 = *(const float4*)&HE[(size_t)ev3.x * CC + lane4];
        float v0 = __int_as_float(ev0.y), v1 = __int_as_float(ev1.y);
        float v2 = __int_as_float(ev2.y), v3 = __int_as_float(ev3.y);
        acc.x += v0 * h0.x + v1 * h1.x + v2 * h2.x + v3 * h3.x;
        acc.y += v0 * h0.y + v1 * h1.y + v2 * h2.y + v3 * h3.y;
        acc.z += v0 * h0.z + v1 * h1.z + v2 * h2.z + v3 * h3.z;
        acc.w += v0 * h0.w + v1 * h1.w + v2 * h2.w + v3 * h3.w;
    }
    for (; e < e1; e++) {
        int2 ev = g_edge[e];
        float v = __int_as_float(ev.y);
        float4 h = *(const float4*)&HE[(size_t)ev.x * CC + lane4];
        acc.x += v * h.x; acc.y += v * h.y; acc.z += v * h.z; acc.w += v * h.w;
    }
    *(float4*)&P[(size_t)warp * CC + lane4] = acc;
}

// ---------------- even-layer GEMM (K=256, A2 = P), register-pipelined --------------
template <bool ADD_RES, bool RED, bool WRITE_X>
__global__ __launch_bounds__(NTHR, 1)
void gemm_lap(const float* __restrict__ A1, const float* __restrict__ A2,
              const __nv_bfloat16* __restrict__ Wh, const __nv_bfloat16* __restrict__ Wl,
              const float* __restrict__ bias, const float* __restrict__ res,
              const float* __restrict__ mask,
              float* __restrict__ outx, float* __restrict__ outhe) {
    extern __shared__ char smem[];
    const uint32_t sb = smem_u32(smem);
    const int tid = threadIdx.x;
    const int wid = tid >> 5, lane = tid & 31;
    const int wm = wid & 7, wn = wid >> 3;     // 8 x 2 warp grid, tile 16x64
    const int m0 = blockIdx.x * 128;
    const int gid = lane >> 2, tid4 = lane & 3;
    const int frow = tid >> 2;
    const int fcol = (tid & 3) * 32;
    const bool rowok = (m0 + frow) < NN;

    stage_B_async(sb, 2 * ARR, Wh, Wl, 0,   frow, fcol);
    cp_commit();
    stage_B_async(sb, 4 * ARR, Wh, Wl, 128, frow, fcol);
    cp_commit();

    stage_A(A1, smem, m0, frow, fcol, rowok);

    // prefetch A2 (P) into registers — lands under chunk0 MMAs
    float4 a2[8];
    ldg_A(a2, A2, m0, frow, fcol, rowok);

    cp_wait_group<1>();
    __syncthreads();

    float acc[8][4] = {};
    const uint32_t aOff = (uint32_t)(((wm * 16 + (lane & 15)) * STRD + (lane >> 4) * 8) * 2);
    const uint32_t bOff = (uint32_t)(((wn * 64 + (lane & 7) + ((lane >> 4) * 8)) * STRD +
                                      ((lane >> 3) & 1) * 8) * 2);
    do_chunk(sb + aOff, sb + 2 * ARR + bOff, acc);
    __syncthreads();

    sts_A(a2, smem, frow, fcol);

    // prefetch residuals — land under chunk1 MMAs
    float2 rr[2][8];
    if (ADD_RES) ldg_res(rr, res, m0, wm, wn, gid, tid4);

    cp_wait_group<0>();
    __syncthreads();
    do_chunk(sb + aOff, sb + 4 * ARR + bOff, acc);

    epilogue<ADD_RES, RED, WRITE_X>(acc, rr, smem, bias, mask, outx, outhe,
                                    m0, wm, wn, gid, tid4, tid, lane, blockIdx.x);
}

// ---------------- odd-layer GEMM (K=128), register-pipelined ----------------
template <bool ADD_RES, bool RED, bool WRITE_X>
__global__ __launch_bounds__(NTHR, 1)
void gemm_avg(const float* __restrict__ A1,
              const __nv_bfloat16* __restrict__ Wh, const __nv_bfloat16* __restrict__ Wl,
              const float* __restrict__ bias, const float* __restrict__ res,
              const float* __restrict__ mask,
              float* __restrict__ outx, float* __restrict__ outhe) {
    extern __shared__ char smem[];
    const uint32_t sb = smem_u32(smem);
    const int tid = threadIdx.x;
    const int wid = tid >> 5, lane = tid & 31;
    const int wm = wid & 7, wn = wid >> 3;
    const int m0 = blockIdx.x * 128;
    const int gid = lane >> 2, tid4 = lane & 3;
    const int frow = tid >> 2;
    const int fcol = (tid & 3) * 32;
    const bool rowok = (m0 + frow) < NN;

    stage_B_async(sb, 2 * ARR, Wh, Wl, 0, frow, fcol);
    cp_commit();
    stage_A(A1, smem, m0, frow, fcol, rowok);

    // prefetch residuals — land under chunk0 MMAs
    float2 rr[2][8];
    if (ADD_RES) ldg_res(rr, res, m0, wm, wn, gid, tid4);

    cp_wait_group<0>();
    __syncthreads();

    float acc[8][4] = {};
    const uint32_t aOff = (uint32_t)(((wm * 16 + (lane & 15)) * STRD + (lane >> 4) * 8) * 2);
    const uint32_t bOff = (uint32_t)(((wn * 64 + (lane & 7) + ((lane >> 4) * 8)) * STRD +
                                      ((lane >> 3) & 1) * 8) * 2);
    do_chunk(sb + aOff, sb + 2 * ARR + bOff, acc);

    epilogue<ADD_RES, RED, WRITE_X>(acc, rr, smem, bias, mask, outx, outhe,
                                    m0, wm, wn, gid, tid4, tid, lane, blockIdx.x);
}

// ---------------- final ----------------
__global__ void final_kernel(const float* __restrict__ HE, const float* __restrict__ W2,
                             const float* __restrict__ b2, const float* __restrict__ in,
                             float* __restrict__ out) {
    int warp = (blockIdx.x * blockDim.x + threadIdx.x) >> 5;
    int lane = threadIdx.x & 31;
    if (warp >= NN) return;
    float4 x = *(const float4*)&HE[(size_t)warp * CC + lane * 4];
    float4 w = *(const float4*)&W2[lane * 4];
    float s = x.x * w.x + x.y * w.y + x.z * w.z + x.w * w.w;
#pragma unroll
    for (int o = 16; o > 0; o >>= 1) s += __shfl_down_sync(0xffffffffu, s, o);
    if (lane == 0) out[warp] = s + b2[0] + in[warp * 3];
}

// ---------------- host launch ----------------
extern "C" void kernel_launch(void* const* d_in, const int* in_sizes, int n_in,
                              void* d_out, int out_size) {
    const int*   L_row  = (const int*)d_in[0];
    const int*   L_col  = (const int*)d_in[1];
    const float* L_val  = (const float*)d_in[2];
    const float* mask   = (const float*)d_in[3];
    const float* inputs = (const float*)d_in[4];
    const float* W1     = (const float*)d_in[5];
    const float* b1     = (const float*)d_in[6];
    const float* BW     = (const float*)d_in[7];
    const float* Bb     = (const float*)d_in[8];
    const float* W2     = (const float*)d_in[9];
    const float* b2     = (const float*)d_in[10];
    float* out = (float*)d_out;

    float *B0, *HE, *P, *cvec;
    __nv_bfloat16 *Wh, *Wl;
    cudaGetSymbolAddress((void**)&B0, g_B0);
    cudaGetSymbolAddress((void**)&HE, g_HE);
    cudaGetSymbolAddress((void**)&P,  g_P);
    cudaGetSymbolAddress((void**)&cvec, g_cvec);
    cudaGetSymbolAddress((void**)&Wh, g_Wh);
    cudaGetSymbolAddress((void**)&Wl, g_Wl);

    static bool attr_done = false;
    if (!attr_done) {
        cudaFuncSetAttribute(gemm_lap<false, false, false>, cudaFuncAttributeMaxDynamicSharedMemorySize, SMTOT_L);
        cudaFuncSetAttribute(gemm_lap<true,  true,  true>,  cudaFuncAttributeMaxDynamicSharedMemorySize, SMTOT_L);
        cudaFuncSetAttribute(gemm_lap<true,  false, false>, cudaFuncAttributeMaxDynamicSharedMemorySize, SMTOT_L);
        cudaFuncSetAttribute(gemm_avg<false, true,  false>, cudaFuncAttributeMaxDynamicSharedMemorySize, SMTOT_O);
        cudaFuncSetAttribute(gemm_avg<true,  false, true>,  cudaFuncAttributeMaxDynamicSharedMemorySize, SMTOT_O);
        attr_done = true;
    }

    // ---- setup (per replay) ----
    zero2_kernel<<<(NN + 255) / 256, 256>>>();
    hist_kernel<<<(NE + 255) / 256, 256>>>(L_row);
    scan1_kernel<<<SCAN_NCHUNK, SCAN_CHUNK>>>();
    scan23_kernel<<<SCAN_NCHUNK, SCAN_CHUNK>>>();
    fill_kernel<<<(NE + 255) / 256, 256>>>(L_row, L_col, L_val);
    masksum_kernel<<<1, 1024>>>(mask);
    wprep_kernel<<<(NSTEPS * 128 * 256 + 255) / 256, 256>>>(BW);

    conv1_kernel<<<(NN * CC + 255) / 256, 256>>>(inputs, W1, b1, B0, HE);

    const int LAP_GRID = (NN * 32 + 255) / 256;

    for (int i = 0; i < NLAYERS; i++) {
        for (int j = 0; j < 2; j++) {
            int step = i * 2 + j;
            const __nv_bfloat16* Whs = Wh + (size_t)step * 128 * 256;
            const __nv_bfloat16* Wls = Wl + (size_t)step * 128 * 256;
            const float* b = Bb + (size_t)step * CC;
            bool last = (step == NSTEPS - 1);

            if ((i & 1) == 0) {
                lap_kernel<<<LAP_GRID, 256>>>(HE, P);
                if (j == 0)
                    gemm_lap<false, false, false><<<GGRID, NTHR, SMTOT_L>>>(
                        HE, P, Whs, Wls, b, nullptr, mask, nullptr, HE);
                else if (!last)
                    gemm_lap<true, true, true><<<GGRID, NTHR, SMTOT_L>>>(
                        HE, P, Whs, Wls, b, B0, mask, B0, HE);
                else
                    gemm_lap<true, false, false><<<GGRID, NTHR, SMTOT_L>>>(
                        HE, P, Whs, Wls, b, B0, mask, nullptr, HE);
            } else {
                cvec_kernel<<<1, 512>>>(BW + (size_t)step * 256 * CC + 128 * CC, b);
                if (j == 0)
                    gemm_avg<false, true, false><<<GGRID, NTHR, SMTOT_O>>>(
                        HE, Whs, Wls, cvec, nullptr, mask, nullptr, HE);
                else
                    gemm_avg<true, false, true><<<GGRID, NTHR, SMTOT_O>>>(
                        HE, Whs, Wls, cvec, B0, mask, B0, HE);
            }
        }
    }

    final_kernel<<<(NN * 32 + 1023) / 1024, 1024>>>(HE, W2, b2, inputs, out);

    (void)in_sizes; (void)n_in; (void)out_size;
}